// round 4
// baseline (speedup 1.0000x reference)
#include <cuda_runtime.h>

// YOLOv2 loss, B=64, A=5, C=80, G=32, N=50. Single-kernel, last-block combine.
#define NGT 50
#define MAIN_BLOCKS 320          // 64 batches x 5 anchor-segments of 1024 boxes (4 boxes/thread)
#define GATH_BLOCKS 400          // 3200 GTs / 8 warps per 256-thread block
#define TOTAL_BLOCKS (MAIN_BLOCKS + GATH_BLOCKS)

__device__ float g_noobj[MAIN_BLOCKS];
__device__ float g_prior[MAIN_BLOCKS];
__device__ float g_coord[GATH_BLOCKS];
__device__ float g_obj[GATH_BLOCKS];
__device__ float g_cls[GATH_BLOCKS];
__device__ unsigned int g_count = 0;

__device__ __forceinline__ float sigm(float x) { return 1.0f / (1.0f + __expf(-x)); }

__global__ void __launch_bounds__(256) fused_kernel(const float* __restrict__ pred,
                                                    const float* __restrict__ gt,
                                                    const float* __restrict__ anc,
                                                    const int* __restrict__ seen,
                                                    float* __restrict__ out)
{
    int tid = threadIdx.x;

    if (blockIdx.x < MAIN_BLOCKS) {
        // ============== MAIN PATH: noobj + prior over all 327680 boxes ==============
        __shared__ float4 sbox[NGT];
        __shared__ float  ssa[NGT];          // 0.375 * gt_area  (= 0.6/1.6 * sa)
        __shared__ unsigned char flag[1024]; // best-box marks for this segment
        __shared__ float  sred[16];

        int b   = blockIdx.x / 5;
        int seg = blockIdx.x % 5;            // == anchor index for this whole block
        const float* pp = pred + (((size_t)(b * 425 + seg * 85)) << 10);
        int c0 = tid, c1 = tid + 256, c2 = tid + 512, c3 = tid + 768;

        // issue all global loads up front
        float dx0 = pp[c0],        dx1 = pp[c1],        dx2 = pp[c2],        dx3 = pp[c3];
        float dy0 = pp[c0 + 1024], dy1 = pp[c1 + 1024], dy2 = pp[c2 + 1024], dy3 = pp[c3 + 1024];
        float tw0 = pp[c0 + 2048], tw1 = pp[c1 + 2048], tw2 = pp[c2 + 2048], tw3 = pp[c3 + 2048];
        float th0 = pp[c0 + 3072], th1 = pp[c1 + 3072], th2 = pp[c2 + 3072], th3 = pp[c3 + 3072];
        float to0 = pp[c0 + 4096], to1 = pp[c1 + 4096], to2 = pp[c2 + 4096], to3 = pp[c3 + 4096];

        flag[tid] = 0; flag[tid + 256] = 0; flag[tid + 512] = 0; flag[tid + 768] = 0;

        int mybb = -1;
        if (tid < NGT) {
            const float* g = gt + (size_t)(b * NGT + tid) * 7;
            float gdx = g[0], gdy = g[1], gx = g[2], gy = g[3], gw = g[4], gh = g[5];
            float ga = gw * gh;
            float best = -1.0f; int bp = 0;
            #pragma unroll
            for (int a = 0; a < 5; a++) {
                float aw = __ldg(&anc[2 * a]), ah = __ldg(&anc[2 * a + 1]);
                float it = fminf(gw, aw) * fminf(gh, ah);
                float iou = it / (ga + aw * ah - it);
                if (iou > best) { best = iou; bp = a; }
            }
            mybb = bp * 1024 + (int)gy * 32 + (int)gx;
            float cx = gdx + gx * (1.0f / 32.0f), cy = gdy + gy * (1.0f / 32.0f);
            sbox[tid] = make_float4(cx - 0.5f * gw, cy - 0.5f * gh, cx + 0.5f * gw, cy + 0.5f * gh);
            ssa[tid]  = 0.375f * ga;
        }
        __syncthreads();
        if ((mybb >> 10) == seg) flag[mybb & 1023] = 1;

        float aw = __ldg(&anc[2 * seg]), ah = __ldg(&anc[2 * seg + 1]);
        float sdx0 = sigm(dx0), sdy0 = sigm(dy0), so0 = sigm(to0);
        float sdx1 = sigm(dx1), sdy1 = sigm(dy1), so1 = sigm(to1);
        float sdx2 = sigm(dx2), sdy2 = sigm(dy2), so2 = sigm(to2);
        float sdx3 = sigm(dx3), sdy3 = sigm(dy3), so3 = sigm(to3);
        float cx0 = sdx0 + (float)(c0 & 31) * (1.0f/32.0f), cy0 = sdy0 + (float)(c0 >> 5) * (1.0f/32.0f);
        float cx1 = sdx1 + (float)(c1 & 31) * (1.0f/32.0f), cy1 = sdy1 + (float)(c1 >> 5) * (1.0f/32.0f);
        float cx2 = sdx2 + (float)(c2 & 31) * (1.0f/32.0f), cy2 = sdy2 + (float)(c2 >> 5) * (1.0f/32.0f);
        float cx3 = sdx3 + (float)(c3 & 31) * (1.0f/32.0f), cy3 = sdy3 + (float)(c3 >> 5) * (1.0f/32.0f);
        float pw0 = aw * __expf(tw0), ph0 = ah * __expf(th0);
        float pw1 = aw * __expf(tw1), ph1 = ah * __expf(th1);
        float pw2 = aw * __expf(tw2), ph2 = ah * __expf(th2);
        float pw3 = aw * __expf(tw3), ph3 = ah * __expf(th3);
        float x10 = cx0 - 0.5f*pw0, y10 = cy0 - 0.5f*ph0, x20 = cx0 + 0.5f*pw0, y20 = cy0 + 0.5f*ph0;
        float x11 = cx1 - 0.5f*pw1, y11 = cy1 - 0.5f*ph1, x21 = cx1 + 0.5f*pw1, y21 = cy1 + 0.5f*ph1;
        float x12 = cx2 - 0.5f*pw2, y12 = cy2 - 0.5f*ph2, x22 = cx2 + 0.5f*pw2, y22 = cy2 + 0.5f*ph2;
        float x13 = cx3 - 0.5f*pw3, y13 = cy3 - 0.5f*ph3, x23 = cx3 + 0.5f*pw3, y23 = cy3 + 0.5f*ph3;
        // over-test:  iou > 0.6  <=>  inter - 0.375*sa > 0.375*sb
        float t0_ = 0.375f * pw0 * ph0, t1_ = 0.375f * pw1 * ph1;
        float t2_ = 0.375f * pw2 * ph2, t3_ = 0.375f * pw3 * ph3;
        __syncthreads();

        float m0 = -1e30f, m1 = -1e30f, m2 = -1e30f, m3 = -1e30f;
        #pragma unroll 5
        for (int n = 0; n < NGT; n++) {
            float4 gb = sbox[n]; float s6 = ssa[n];
            float w0 = fminf(x20, gb.z) - fmaxf(x10, gb.x);
            float h0 = fminf(y20, gb.w) - fmaxf(y10, gb.y);
            m0 = fmaxf(m0, fmaxf(w0, 0.0f) * fmaxf(h0, 0.0f) - s6);
            float w1 = fminf(x21, gb.z) - fmaxf(x11, gb.x);
            float h1 = fminf(y21, gb.w) - fmaxf(y11, gb.y);
            m1 = fmaxf(m1, fmaxf(w1, 0.0f) * fmaxf(h1, 0.0f) - s6);
            float w2 = fminf(x22, gb.z) - fmaxf(x12, gb.x);
            float h2 = fminf(y22, gb.w) - fmaxf(y12, gb.y);
            m2 = fmaxf(m2, fmaxf(w2, 0.0f) * fmaxf(h2, 0.0f) - s6);
            float w3 = fminf(x23, gb.z) - fmaxf(x13, gb.x);
            float h3 = fminf(y23, gb.w) - fmaxf(y13, gb.y);
            m3 = fmaxf(m3, fmaxf(w3, 0.0f) * fmaxf(h3, 0.0f) - s6);
        }
        bool ib0 = flag[c0] != 0, ib1 = flag[c1] != 0, ib2 = flag[c2] != 0, ib3 = flag[c3] != 0;
        float no = 0.0f, pr = 0.0f;
        if (!ib0 && !(m0 > t0_)) no += so0 * so0;
        if (!ib1 && !(m1 > t1_)) no += so1 * so1;
        if (!ib2 && !(m2 > t2_)) no += so2 * so2;
        if (!ib3 && !(m3 > t3_)) no += so3 * so3;
        if (!ib0) { float d0 = sdx0 - 0.015625f, d1 = sdy0 - 0.015625f; pr += d0*d0 + d1*d1 + tw0*tw0 + th0*th0; }
        if (!ib1) { float d0 = sdx1 - 0.015625f, d1 = sdy1 - 0.015625f; pr += d0*d0 + d1*d1 + tw1*tw1 + th1*th1; }
        if (!ib2) { float d0 = sdx2 - 0.015625f, d1 = sdy2 - 0.015625f; pr += d0*d0 + d1*d1 + tw2*tw2 + th2*th2; }
        if (!ib3) { float d0 = sdx3 - 0.015625f, d1 = sdy3 - 0.015625f; pr += d0*d0 + d1*d1 + tw3*tw3 + th3*th3; }

        #pragma unroll
        for (int off = 16; off; off >>= 1) {
            no += __shfl_down_sync(0xffffffffu, no, off);
            pr += __shfl_down_sync(0xffffffffu, pr, off);
        }
        int wid = tid >> 5, lane = tid & 31;
        if (lane == 0) { sred[wid] = no; sred[8 + wid] = pr; }
        __syncthreads();
        if (tid == 0) {
            float s = 0.0f;
            #pragma unroll
            for (int i = 0; i < 8; i++) s += sred[i];
            g_noobj[blockIdx.x] = s;
        }
        if (tid == 32) {
            float s = 0.0f;
            #pragma unroll
            for (int i = 0; i < 8; i++) s += sred[8 + i];
            g_prior[blockIdx.x] = s;
        }
    } else {
        // ============== GATHER PATH: coord + obj + cls at 3200 best boxes ==============
        __shared__ float sc[8], so_[8], sl[8];
        int gb_ = blockIdx.x - MAIN_BLOCKS;
        int wid = tid >> 5, lane = tid & 31;
        int gtid = gb_ * 8 + wid;
        int b = gtid / NGT;

        const float* g = gt + (size_t)gtid * 7;
        float gdx = g[0], gdy = g[1], gx = g[2], gy = g[3], gw = g[4], gh = g[5];
        int k = (int)g[6];
        float ga = gw * gh;
        float best = -1.0f; int bp = 0;
        #pragma unroll
        for (int a = 0; a < 5; a++) {
            float aw = __ldg(&anc[2 * a]), ah = __ldg(&anc[2 * a + 1]);
            float it = fminf(gw, aw) * fminf(gh, ah);
            float iou = it / (ga + aw * ah - it);
            if (iou > best) { best = iou; bp = a; }
        }
        int cell = (int)gy * 32 + (int)gx;
        const float* pp = pred + (((size_t)(b * 425 + bp * 85)) << 10) + cell;

        // one-pass softmax-MSE: sum_c (p_c - 1[c=k])^2 = Q/S^2 - 2 e_k/S + 1
        float S = 0.0f, Q = 0.0f, ek = 0.0f;
        {
            float e0 = __expf(pp[(size_t)(5 + lane) << 10]);  S += e0; Q += e0 * e0; if (lane == k) ek = e0;
            float e1 = __expf(pp[(size_t)(37 + lane) << 10]); S += e1; Q += e1 * e1; if (lane + 32 == k) ek = e1;
            if (lane < 16) {
                float e2 = __expf(pp[(size_t)(69 + lane) << 10]); S += e2; Q += e2 * e2; if (lane + 64 == k) ek = e2;
            }
        }
        #pragma unroll
        for (int off = 16; off; off >>= 1) {
            S  += __shfl_xor_sync(0xffffffffu, S,  off);
            Q  += __shfl_xor_sync(0xffffffffu, Q,  off);
            ek += __shfl_xor_sync(0xffffffffu, ek, off);
        }

        float sdx = sigm(pp[0]), sdy = sigm(pp[1024]);
        float tw = pp[2048], th = pp[3072], sobj = sigm(pp[4096]);
        float aw = __ldg(&anc[2 * bp]), ah = __ldg(&anc[2 * bp + 1]);
        float d0 = sdx - gdx, d1 = sdy - gdy;
        float d2 = tw - (__logf(gw) - __logf(aw));
        float d3 = th - (__logf(gh) - __logf(ah));
        float coord = d0*d0 + d1*d1 + d2*d2 + d3*d3;

        float cx = sdx + (float)(cell & 31) * (1.0f / 32.0f);
        float cy = sdy + (float)(cell >> 5) * (1.0f / 32.0f);
        float pw = aw * __expf(tw), ph = ah * __expf(th);
        float gx1 = (gdx + gx * (1.0f / 32.0f)) - 0.5f * gw;
        float gy1 = (gdy + gy * (1.0f / 32.0f)) - 0.5f * gh;
        float w = fminf(cx + 0.5f * pw, gx1 + gw) - fmaxf(cx - 0.5f * pw, gx1);
        float h = fminf(cy + 0.5f * ph, gy1 + gh) - fmaxf(cy - 0.5f * ph, gy1);
        float inter = fmaxf(w, 0.0f) * fmaxf(h, 0.0f);
        float iou_t = inter / (ga + pw * ph - inter);
        float di = sobj - iou_t;
        float obj = di * di;
        float invS = 1.0f / S;
        float cls = fmaf(Q * invS, invS, fmaf(-2.0f * ek, invS, 1.0f));

        if (lane == 0) { sc[wid] = coord; so_[wid] = obj; sl[wid] = cls; }
        __syncthreads();
        if (tid == 0) {
            float tc = 0.f, to_ = 0.f, tl = 0.f;
            #pragma unroll
            for (int i = 0; i < 8; i++) { tc += sc[i]; to_ += so_[i]; tl += sl[i]; }
            g_coord[gb_] = tc;
            g_obj[gb_]   = to_;
            g_cls[gb_]   = tl;
        }
    }

    // ---------------- last-block deterministic final combine ----------------
    __shared__ bool is_last;
    __shared__ float sm[40];
    __syncthreads();
    if (threadIdx.x == 0) {
        __threadfence();
        unsigned int c = atomicAdd(&g_count, 1u);
        is_last = (c == TOTAL_BLOCKS - 1);
    }
    __syncthreads();
    if (!is_last) return;
    __threadfence();  // make all blocks' partials visible

    float a0 = 0.f, a1 = 0.f, a2 = 0.f, a3 = 0.f, a4 = 0.f;
    for (int i = tid; i < MAIN_BLOCKS; i += 256) { a0 += g_noobj[i]; a1 += g_prior[i]; }
    for (int i = tid; i < GATH_BLOCKS; i += 256) { a2 += g_coord[i]; a3 += g_obj[i]; a4 += g_cls[i]; }
    #pragma unroll
    for (int off = 16; off; off >>= 1) {
        a0 += __shfl_down_sync(0xffffffffu, a0, off);
        a1 += __shfl_down_sync(0xffffffffu, a1, off);
        a2 += __shfl_down_sync(0xffffffffu, a2, off);
        a3 += __shfl_down_sync(0xffffffffu, a3, off);
        a4 += __shfl_down_sync(0xffffffffu, a4, off);
    }
    int wid2 = tid >> 5, lane2 = tid & 31;
    if (lane2 == 0) {
        sm[wid2] = a0; sm[8 + wid2] = a1; sm[16 + wid2] = a2; sm[24 + wid2] = a3; sm[32 + wid2] = a4;
    }
    __syncthreads();
    if (tid == 0) {
        float t0 = 0.f, t1 = 0.f, t2 = 0.f, t3 = 0.f, t4 = 0.f;
        #pragma unroll
        for (int i = 0; i < 8; i++) {
            t0 += sm[i]; t1 += sm[8 + i]; t2 += sm[16 + i]; t3 += sm[24 + i]; t4 += sm[32 + i];
        }
        float lp = (seen[0] < 12800) ? 0.01f : 0.0f;
        out[0] = t4 + t0 + 5.0f * t3 + t2 + lp * t1;
        g_count = 0;   // reset for next graph replay
    }
}

extern "C" void kernel_launch(void* const* d_in, const int* in_sizes, int n_in,
                              void* d_out, int out_size) {
    const float* pred = (const float*)d_in[0];
    const float* gt   = (const float*)d_in[1];
    const float* anc  = (const float*)d_in[2];
    const int*   seen = (const int*)d_in[3];
    (void)in_sizes; (void)n_in; (void)out_size;

    fused_kernel<<<TOTAL_BLOCKS, 256>>>(pred, gt, anc, seen, (float*)d_out);
}

// round 5
// speedup vs baseline: 1.1254x; 1.1254x over previous
#include <cuda_runtime.h>

// YOLOv2 loss, B=64, A=5, C=80, G=32, N=50. Single kernel, last-block combine.
#define NGT 50
#define MAIN_BLOCKS 640          // 64 batches x 10 segs of 512 boxes (2 boxes/thread)
#define GATH_BLOCKS 400          // 3200 GTs / 8 warps per 256-thread block
#define TOTAL_BLOCKS (MAIN_BLOCKS + GATH_BLOCKS)

__device__ float g_noobj[MAIN_BLOCKS];
__device__ float g_prior[MAIN_BLOCKS];
__device__ float g_coord[GATH_BLOCKS];
__device__ float g_obj[GATH_BLOCKS];
__device__ float g_cls[GATH_BLOCKS];
__device__ unsigned int g_count = 0;

__device__ __forceinline__ float sigm(float x) { return 1.0f / (1.0f + __expf(-x)); }

__global__ void __launch_bounds__(256) fused_kernel(const float* __restrict__ pred,
                                                    const float* __restrict__ gt,
                                                    const float* __restrict__ anc,
                                                    const int* __restrict__ seen,
                                                    float* __restrict__ out)
{
    int tid = threadIdx.x;

    if (blockIdx.x < MAIN_BLOCKS) {
        // ============== MAIN PATH: noobj + prior over all 327680 boxes ==============
        __shared__ float4 sbox[NGT];
        __shared__ float  ssa[NGT];          // 0.375 * gt_area  (= 0.6/1.6 * sa)
        __shared__ unsigned char flag[512];  // best-box marks for this block's range
        __shared__ float  sred[16];

        int b    = blockIdx.x / 10;
        int base = (blockIdx.x % 10) * 512;
        int idx0 = base + tid, idx1 = idx0 + 256;
        int a0 = idx0 >> 10, c0 = idx0 & 1023;
        int a1 = idx1 >> 10, c1 = idx1 & 1023;
        const float* p0 = pred + (((size_t)(b * 425 + a0 * 85)) << 10) + c0;
        const float* p1 = pred + (((size_t)(b * 425 + a1 * 85)) << 10) + c1;
        // issue all global loads up front (latency hidden behind prep)
        float dx0 = p0[0], dy0 = p0[1024], tw0 = p0[2048], th0 = p0[3072], to0 = p0[4096];
        float dx1 = p1[0], dy1 = p1[1024], tw1 = p1[2048], th1 = p1[3072], to1 = p1[4096];

        flag[tid] = 0; flag[tid + 256] = 0;

        int mybb = -1;
        if (tid < NGT) {
            const float* g = gt + (size_t)(b * NGT + tid) * 7;
            float gdx = g[0], gdy = g[1], gx = g[2], gy = g[3], gw = g[4], gh = g[5];
            float ga = gw * gh;
            float best = -1.0f; int bp = 0;
            #pragma unroll
            for (int a = 0; a < 5; a++) {
                float aw = __ldg(&anc[2 * a]), ah = __ldg(&anc[2 * a + 1]);
                float it = fminf(gw, aw) * fminf(gh, ah);
                float iou = it / (ga + aw * ah - it);
                if (iou > best) { best = iou; bp = a; }
            }
            mybb = bp * 1024 + (int)gy * 32 + (int)gx;
            float cx = gdx + gx * (1.0f / 32.0f), cy = gdy + gy * (1.0f / 32.0f);
            sbox[tid] = make_float4(cx - 0.5f * gw, cy - 0.5f * gh, cx + 0.5f * gw, cy + 0.5f * gh);
            ssa[tid]  = 0.375f * ga;
        }
        __syncthreads();
        if (mybb >= base && mybb < base + 512) flag[mybb - base] = 1;

        float sdx0 = sigm(dx0), sdy0 = sigm(dy0), so0 = sigm(to0);
        float sdx1 = sigm(dx1), sdy1 = sigm(dy1), so1 = sigm(to1);
        float cx0 = sdx0 + (float)(c0 & 31) * (1.0f / 32.0f);
        float cy0 = sdy0 + (float)(c0 >> 5) * (1.0f / 32.0f);
        float cx1 = sdx1 + (float)(c1 & 31) * (1.0f / 32.0f);
        float cy1 = sdy1 + (float)(c1 >> 5) * (1.0f / 32.0f);
        float pw0 = __ldg(&anc[2 * a0]) * __expf(tw0), ph0 = __ldg(&anc[2 * a0 + 1]) * __expf(th0);
        float pw1 = __ldg(&anc[2 * a1]) * __expf(tw1), ph1 = __ldg(&anc[2 * a1 + 1]) * __expf(th1);
        float x10 = cx0 - 0.5f*pw0, y10 = cy0 - 0.5f*ph0, x20 = cx0 + 0.5f*pw0, y20 = cy0 + 0.5f*ph0;
        float x11 = cx1 - 0.5f*pw1, y11 = cy1 - 0.5f*ph1, x21 = cx1 + 0.5f*pw1, y21 = cy1 + 0.5f*ph1;
        // over-test:  iou > 0.6  <=>  inter - 0.375*sa > 0.375*sb   (division-free)
        float t0_ = 0.375f * pw0 * ph0, t1_ = 0.375f * pw1 * ph1;
        __syncthreads();

        float m0 = -1e30f, m1 = -1e30f;
        #pragma unroll 10
        for (int n = 0; n < NGT; n++) {
            float4 gb = sbox[n]; float s6 = ssa[n];
            // h is NOT clamped: if h<0 then max(w,0)*h <= 0 < 0.375*sb, never triggers.
            float w0 = fminf(x20, gb.z) - fmaxf(x10, gb.x);
            float h0 = fminf(y20, gb.w) - fmaxf(y10, gb.y);
            m0 = fmaxf(m0, fmaf(fmaxf(w0, 0.0f), h0, -s6));
            float w1 = fminf(x21, gb.z) - fmaxf(x11, gb.x);
            float h1 = fminf(y21, gb.w) - fmaxf(y11, gb.y);
            m1 = fmaxf(m1, fmaf(fmaxf(w1, 0.0f), h1, -s6));
        }
        bool ib0 = flag[tid] != 0, ib1 = flag[tid + 256] != 0;
        float no = 0.0f, pr = 0.0f;
        if (!ib0 && !(m0 > t0_)) no += so0 * so0;
        if (!ib1 && !(m1 > t1_)) no += so1 * so1;
        if (!ib0) { float d0 = sdx0 - 0.015625f, d1 = sdy0 - 0.015625f; pr += d0*d0 + d1*d1 + tw0*tw0 + th0*th0; }
        if (!ib1) { float d0 = sdx1 - 0.015625f, d1 = sdy1 - 0.015625f; pr += d0*d0 + d1*d1 + tw1*tw1 + th1*th1; }

        #pragma unroll
        for (int off = 16; off; off >>= 1) {
            no += __shfl_down_sync(0xffffffffu, no, off);
            pr += __shfl_down_sync(0xffffffffu, pr, off);
        }
        int wid = tid >> 5, lane = tid & 31;
        if (lane == 0) { sred[wid] = no; sred[8 + wid] = pr; }
        __syncthreads();
        if (tid == 0) {
            float s = 0.0f;
            #pragma unroll
            for (int i = 0; i < 8; i++) s += sred[i];
            g_noobj[blockIdx.x] = s;
        }
        if (tid == 32) {
            float s = 0.0f;
            #pragma unroll
            for (int i = 0; i < 8; i++) s += sred[8 + i];
            g_prior[blockIdx.x] = s;
        }
    } else {
        // ============== GATHER PATH: coord + obj + cls at 3200 best boxes ==============
        __shared__ float sc[8], so_[8], sl[8];
        int gb_ = blockIdx.x - MAIN_BLOCKS;
        int wid = tid >> 5, lane = tid & 31;
        int gtid = gb_ * 8 + wid;
        int b = gtid / NGT;

        const float* g = gt + (size_t)gtid * 7;   // broadcast loads across warp
        float gdx = g[0], gdy = g[1], gx = g[2], gy = g[3], gw = g[4], gh = g[5];
        int k = (int)g[6];
        float ga = gw * gh;
        float best = -1.0f; int bp = 0;
        #pragma unroll
        for (int a = 0; a < 5; a++) {
            float aw = __ldg(&anc[2 * a]), ah = __ldg(&anc[2 * a + 1]);
            float it = fminf(gw, aw) * fminf(gh, ah);
            float iou = it / (ga + aw * ah - it);
            if (iou > best) { best = iou; bp = a; }
        }
        int cell = (int)gy * 32 + (int)gx;
        const float* pp = pred + (((size_t)(b * 425 + bp * 85)) << 10) + cell;

        // one-pass softmax-MSE: sum_c (p_c - 1[c=k])^2 = Q/S^2 - 2 e_k/S + 1
        float S = 0.0f, Q = 0.0f, ek = 0.0f;
        {
            float e0 = __expf(pp[(size_t)(5 + lane) << 10]);  S += e0; Q += e0 * e0; if (lane == k) ek = e0;
            float e1 = __expf(pp[(size_t)(37 + lane) << 10]); S += e1; Q += e1 * e1; if (lane + 32 == k) ek = e1;
            if (lane < 16) {
                float e2 = __expf(pp[(size_t)(69 + lane) << 10]); S += e2; Q += e2 * e2; if (lane + 64 == k) ek = e2;
            }
        }
        #pragma unroll
        for (int off = 16; off; off >>= 1) {
            S  += __shfl_xor_sync(0xffffffffu, S,  off);
            Q  += __shfl_xor_sync(0xffffffffu, Q,  off);
            ek += __shfl_xor_sync(0xffffffffu, ek, off);
        }

        float sdx = sigm(pp[0]), sdy = sigm(pp[1024]);
        float tw = pp[2048], th = pp[3072], sobj = sigm(pp[4096]);
        float aw = __ldg(&anc[2 * bp]), ah = __ldg(&anc[2 * bp + 1]);
        float d0 = sdx - gdx, d1 = sdy - gdy;
        float d2 = tw - (__logf(gw) - __logf(aw));
        float d3 = th - (__logf(gh) - __logf(ah));
        float coord = d0*d0 + d1*d1 + d2*d2 + d3*d3;

        float cx = sdx + (float)(cell & 31) * (1.0f / 32.0f);
        float cy = sdy + (float)(cell >> 5) * (1.0f / 32.0f);
        float pw = aw * __expf(tw), ph = ah * __expf(th);
        float gx1 = (gdx + gx * (1.0f / 32.0f)) - 0.5f * gw;
        float gy1 = (gdy + gy * (1.0f / 32.0f)) - 0.5f * gh;
        float w = fminf(cx + 0.5f * pw, gx1 + gw) - fmaxf(cx - 0.5f * pw, gx1);
        float h = fminf(cy + 0.5f * ph, gy1 + gh) - fmaxf(cy - 0.5f * ph, gy1);
        float inter = fmaxf(w, 0.0f) * fmaxf(h, 0.0f);
        float iou_t = inter / (ga + pw * ph - inter);
        float di = sobj - iou_t;
        float obj = di * di;
        float invS = 1.0f / S;
        float cls = fmaf(Q * invS, invS, fmaf(-2.0f * ek, invS, 1.0f));

        if (lane == 0) { sc[wid] = coord; so_[wid] = obj; sl[wid] = cls; }
        __syncthreads();
        if (tid == 0) {
            float tc = 0.f, to_ = 0.f, tl = 0.f;
            #pragma unroll
            for (int i = 0; i < 8; i++) { tc += sc[i]; to_ += so_[i]; tl += sl[i]; }
            g_coord[gb_] = tc;
            g_obj[gb_]   = to_;
            g_cls[gb_]   = tl;
        }
    }

    // ---------------- last-block deterministic final combine ----------------
    __shared__ bool is_last;
    __shared__ float sm[40];
    __syncthreads();
    if (threadIdx.x == 0) {
        __threadfence();
        unsigned int c = atomicAdd(&g_count, 1u);
        is_last = (c == TOTAL_BLOCKS - 1);
    }
    __syncthreads();
    if (!is_last) return;
    __threadfence();  // make all blocks' partials visible

    float a0 = 0.f, a1 = 0.f, a2 = 0.f, a3 = 0.f, a4 = 0.f;
    for (int i = tid; i < MAIN_BLOCKS; i += 256) { a0 += g_noobj[i]; a1 += g_prior[i]; }
    for (int i = tid; i < GATH_BLOCKS; i += 256) { a2 += g_coord[i]; a3 += g_obj[i]; a4 += g_cls[i]; }
    #pragma unroll
    for (int off = 16; off; off >>= 1) {
        a0 += __shfl_down_sync(0xffffffffu, a0, off);
        a1 += __shfl_down_sync(0xffffffffu, a1, off);
        a2 += __shfl_down_sync(0xffffffffu, a2, off);
        a3 += __shfl_down_sync(0xffffffffu, a3, off);
        a4 += __shfl_down_sync(0xffffffffu, a4, off);
    }
    int wid2 = tid >> 5, lane2 = tid & 31;
    if (lane2 == 0) {
        sm[wid2] = a0; sm[8 + wid2] = a1; sm[16 + wid2] = a2; sm[24 + wid2] = a3; sm[32 + wid2] = a4;
    }
    __syncthreads();
    if (tid == 0) {
        float t0 = 0.f, t1 = 0.f, t2 = 0.f, t3 = 0.f, t4 = 0.f;
        #pragma unroll
        for (int i = 0; i < 8; i++) {
            t0 += sm[i]; t1 += sm[8 + i]; t2 += sm[16 + i]; t3 += sm[24 + i]; t4 += sm[32 + i];
        }
        float lp = (seen[0] < 12800) ? 0.01f : 0.0f;
        out[0] = t4 + t0 + 5.0f * t3 + t2 + lp * t1;
        g_count = 0;   // reset for next graph replay
    }
}

extern "C" void kernel_launch(void* const* d_in, const int* in_sizes, int n_in,
                              void* d_out, int out_size) {
    const float* pred = (const float*)d_in[0];
    const float* gt   = (const float*)d_in[1];
    const float* anc  = (const float*)d_in[2];
    const int*   seen = (const int*)d_in[3];
    (void)in_sizes; (void)n_in; (void)out_size;

    fused_kernel<<<TOTAL_BLOCKS, 256>>>(pred, gt, anc, seen, (float*)d_out);
}